// round 1
// baseline (speedup 1.0000x reference)
#include <cuda_runtime.h>
#include <math.h>

#define BATCH 2
#define SEQ   2048
#define DIM   1024
#define NH    16
#define HD    64
#define MTOT  (BATCH*SEQ)   // 4096

// Scratch (allocation-free rule: __device__ globals)
__device__ float g_q[MTOT*DIM];
__device__ float g_k[MTOT*DIM];
__device__ float g_v[MTOT*DIM];
__device__ float g_a[MTOT*DIM];

// ---------------------------------------------------------------------------
// SGEMM: C[M,N] = A[M,K] @ B[K,N] (+ bias over N if bias != nullptr)
// 128x128 block tile, BK=8, 256 threads, 8x8 per-thread microtile.
// ---------------------------------------------------------------------------
__global__ __launch_bounds__(256) void sgemm_kernel(
    const float* __restrict__ A, const float* __restrict__ B,
    float* __restrict__ C, const float* __restrict__ bias,
    int M, int N, int K)
{
    __shared__ float As[8][128];
    __shared__ float Bs[8][128];

    const int tid = threadIdx.x;
    const int bx  = blockIdx.x;   // N tile
    const int by  = blockIdx.y;   // M tile

    const int aRow = tid >> 1;          // 0..127
    const int aCol = (tid & 1) * 4;     // 0 or 4
    const int bRow = tid >> 5;          // 0..7
    const int bCol = (tid & 31) * 4;    // 0..124

    const int ty = tid >> 4;            // 0..15
    const int tx = tid & 15;            // 0..15

    const float* Aptr = A + (by * 128 + aRow) * K + aCol;
    const float* Bptr = B + bRow * N + bx * 128 + bCol;

    float acc[8][8];
    #pragma unroll
    for (int i = 0; i < 8; i++)
        #pragma unroll
        for (int j = 0; j < 8; j++)
            acc[i][j] = 0.0f;

    for (int k0 = 0; k0 < K; k0 += 8) {
        float4 a = *reinterpret_cast<const float4*>(Aptr + k0);
        float4 b = *reinterpret_cast<const float4*>(Bptr + k0 * N);

        As[aCol + 0][aRow] = a.x;
        As[aCol + 1][aRow] = a.y;
        As[aCol + 2][aRow] = a.z;
        As[aCol + 3][aRow] = a.w;
        *reinterpret_cast<float4*>(&Bs[bRow][bCol]) = b;
        __syncthreads();

        #pragma unroll
        for (int kk = 0; kk < 8; kk++) {
            float4 ra0 = *reinterpret_cast<const float4*>(&As[kk][ty * 8]);
            float4 ra1 = *reinterpret_cast<const float4*>(&As[kk][ty * 8 + 4]);
            float4 rb0 = *reinterpret_cast<const float4*>(&Bs[kk][tx * 8]);
            float4 rb1 = *reinterpret_cast<const float4*>(&Bs[kk][tx * 8 + 4]);
            float ra[8] = {ra0.x, ra0.y, ra0.z, ra0.w, ra1.x, ra1.y, ra1.z, ra1.w};
            float rb[8] = {rb0.x, rb0.y, rb0.z, rb0.w, rb1.x, rb1.y, rb1.z, rb1.w};
            #pragma unroll
            for (int i = 0; i < 8; i++)
                #pragma unroll
                for (int j = 0; j < 8; j++)
                    acc[i][j] += ra[i] * rb[j];
        }
        __syncthreads();
    }

    const int row0 = by * 128 + ty * 8;
    const int col0 = bx * 128 + tx * 8;
    const bool has_bias = (bias != nullptr);
    #pragma unroll
    for (int i = 0; i < 8; i++) {
        float4 o0, o1;
        float bv[8];
        #pragma unroll
        for (int j = 0; j < 8; j++)
            bv[j] = acc[i][j] + (has_bias ? bias[col0 + j] : 0.0f);
        o0.x = bv[0]; o0.y = bv[1]; o0.z = bv[2]; o0.w = bv[3];
        o1.x = bv[4]; o1.y = bv[5]; o1.z = bv[6]; o1.w = bv[7];
        *reinterpret_cast<float4*>(&C[(row0 + i) * N + col0])     = o0;
        *reinterpret_cast<float4*>(&C[(row0 + i) * N + col0 + 4]) = o1;
    }
}

// ---------------------------------------------------------------------------
// Flash attention (fp32, causal). One thread owns one q row (q + acc in regs).
// Block: 128 threads = 128 q rows. K/V tiles of 64 rows in shared memory.
// Online softmax, 16-wide kv chunks (rescale acc at most once per chunk).
// ---------------------------------------------------------------------------
__global__ __launch_bounds__(128) void attn_kernel(
    const float* __restrict__ Q, const float* __restrict__ K,
    const float* __restrict__ V, float* __restrict__ O)
{
    __shared__ float Ks[64][64];
    __shared__ float Vs[64][64];

    const int b   = blockIdx.z;
    const int h   = blockIdx.y;
    const int q0  = blockIdx.x * 128;
    const int tid = threadIdx.x;
    const int qi  = q0 + tid;

    const float* Qb = Q + ((long)b * SEQ + qi) * DIM + h * HD;
    float qreg[64];
    #pragma unroll
    for (int d = 0; d < 64; d++)
        qreg[d] = Qb[d] * 0.125f;   // 1/sqrt(64)

    float m = -1e30f;
    float l = 0.0f;
    float acc[64];
    #pragma unroll
    for (int d = 0; d < 64; d++) acc[d] = 0.0f;

    const float* Kbase = K + (long)b * SEQ * DIM + h * HD;
    const float* Vbase = V + (long)b * SEQ * DIM + h * HD;

    const int kv_end = q0 + 128;   // causal: no tile starts past q0+127
    for (int kv0 = 0; kv0 < kv_end; kv0 += 64) {
        __syncthreads();
        // Coalesced tile load: consecutive tid -> consecutive columns
        #pragma unroll
        for (int it = 0; it < 32; it++) {
            int idx = tid + it * 128;
            int r = idx >> 6, c = idx & 63;
            Ks[r][c] = Kbase[(long)(kv0 + r) * DIM + c];
            Vs[r][c] = Vbase[(long)(kv0 + r) * DIM + c];
        }
        __syncthreads();

        #pragma unroll 1
        for (int c4 = 0; c4 < 4; c4++) {
            float s[16];
            float cmax = -1e30f;
            #pragma unroll
            for (int jj = 0; jj < 16; jj++) {
                const int j = c4 * 16 + jj;
                float sv = 0.0f;
                #pragma unroll
                for (int d4 = 0; d4 < 16; d4++) {
                    float4 kk = *reinterpret_cast<const float4*>(&Ks[j][d4 * 4]);
                    sv += qreg[d4 * 4 + 0] * kk.x;
                    sv += qreg[d4 * 4 + 1] * kk.y;
                    sv += qreg[d4 * 4 + 2] * kk.z;
                    sv += qreg[d4 * 4 + 3] * kk.w;
                }
                if (kv0 + j > qi) sv = -1e30f;   // causal mask
                s[jj] = sv;
                cmax = fmaxf(cmax, sv);
            }
            if (cmax > m) {
                float scale = __expf(m - cmax);
                m = cmax;
                l *= scale;
                #pragma unroll
                for (int d = 0; d < 64; d++) acc[d] *= scale;
            }
            #pragma unroll
            for (int jj = 0; jj < 16; jj++) {
                const int j = c4 * 16 + jj;
                float p = __expf(s[jj] - m);
                l += p;
                #pragma unroll
                for (int d4 = 0; d4 < 16; d4++) {
                    float4 vv = *reinterpret_cast<const float4*>(&Vs[j][d4 * 4]);
                    acc[d4 * 4 + 0] += p * vv.x;
                    acc[d4 * 4 + 1] += p * vv.y;
                    acc[d4 * 4 + 2] += p * vv.z;
                    acc[d4 * 4 + 3] += p * vv.w;
                }
            }
        }
    }

    const float inv_l = 1.0f / l;
    float* Ob = O + ((long)b * SEQ + qi) * DIM + h * HD;
    #pragma unroll
    for (int d = 0; d < 64; d++)
        Ob[d] = acc[d] * inv_l;
}

// ---------------------------------------------------------------------------
// Launch
// ---------------------------------------------------------------------------
extern "C" void kernel_launch(void* const* d_in, const int* in_sizes, int n_in,
                              void* d_out, int out_size)
{
    const float* x  = (const float*)d_in[0];
    const float* Wq = (const float*)d_in[1];
    const float* Wk = (const float*)d_in[2];
    const float* Wv = (const float*)d_in[3];
    const float* Wo = (const float*)d_in[4];
    const float* bo = (const float*)d_in[5];
    float* out = (float*)d_out;

    float *qp, *kp, *vp, *ap;
    cudaGetSymbolAddress((void**)&qp, g_q);
    cudaGetSymbolAddress((void**)&kp, g_k);
    cudaGetSymbolAddress((void**)&vp, g_v);
    cudaGetSymbolAddress((void**)&ap, g_a);

    const int M = MTOT, N = DIM, K = DIM;
    dim3 gemm_grid(N / 128, M / 128);   // (8, 32)

    sgemm_kernel<<<gemm_grid, 256>>>(x, Wq, qp, nullptr, M, N, K);
    sgemm_kernel<<<gemm_grid, 256>>>(x, Wk, kp, nullptr, M, N, K);
    sgemm_kernel<<<gemm_grid, 256>>>(x, Wv, vp, nullptr, M, N, K);

    dim3 attn_grid(SEQ / 128, NH, BATCH);   // (16, 16, 2)
    attn_kernel<<<attn_grid, 128>>>(qp, kp, vp, ap);

    sgemm_kernel<<<gemm_grid, 256>>>(ap, Wo, out, bo, M, N, K);
}